// round 11
// baseline (speedup 1.0000x reference)
#include <cuda_runtime.h>
#include <cstdint>

// Tridiagonal Thomas solve with precomputed LU factors, chunked with
// exponential-decay halos (|c|,|w| <= 1/3 => 0.268^16 ~ 7e-10 warmup error).
//
// R11: software-pipelined persistent warps. One block == one warp, pinned to
// a 128-column chunk (+16 halo each side); it processes 4 row-group tiles of
// 32 rows, double-buffered: cp.async prefetch of tile t+1 overlaps compute +
// store of tile t, so every warp keeps a read in flight continuously.
// Coefficients staged once per block.

#define L_CHUNK 128
#define HALO    16
#define CW      (L_CHUNK + 2 * HALO)   // 160 columns max per tile
#define ROWS    32                     // rows per tile == threads per block
#define TS      164                    // tile row stride: 41 f4/row; 164%32=4 -> conflict-free .128
#define RG      4                      // row-group tiles per block
#define MAXN    8192

__device__ float g_cc[MAXN];   // cc[i] = c[i-1], cc[0] = 0
__device__ float g_ia[MAXN];   // 1 / a[i]
__device__ float g_w [MAXN];   // b[i] / a[i], w[N-1] = 0

__global__ void setup_coeffs(const float* __restrict__ a,
                             const float* __restrict__ b,
                             const float* __restrict__ c, int N) {
    int i = blockIdx.x * blockDim.x + threadIdx.x;
    if (i < N) {
        g_cc[i] = (i == 0) ? 0.0f : c[i - 1];
        float ia = 1.0f / a[i];
        g_ia[i] = ia;
        g_w[i]  = (i < N - 1) ? b[i] * ia : 0.0f;
    }
}

__device__ __forceinline__ uint32_t smem_u32(const void* p) {
    return (uint32_t)__cvta_generic_to_shared(p);
}

__device__ __forceinline__ void cp16(uint32_t dst, const float* src) {
    asm volatile("cp.async.cg.shared.global [%0], [%1], 16;\n"
                 :: "r"(dst), "l"(src));
}

__global__ void __launch_bounds__(ROWS)
solve_kernel(const float* __restrict__ x, float* __restrict__ z, int N) {
    __shared__ float tile[2][ROWS * TS];           // 2 x 21.0 KB
    __shared__ float cc_s[CW], ia_s[CW], w_s[CW];  // 1.92 KB

    const int lane = threadIdx.x;                   // 0..31
    const int s    = blockIdx.x * L_CHUNK;          // chunk start
    const int c0   = max(s - HALO, 0);              // tile col range [c0, c1)
    const int c1   = min(s + L_CHUNK + HALO, N);
    const int ncol = c1 - c0;                       // 144 or 160, multiple of 16
    const int nf4  = ncol >> 2;                     // 36 or 40 float4 per row
    const int jlo  = s - c0;                        // 0 (first chunk) or 16
    const int g0   = blockIdx.y * RG;               // first row-group index

    // ---- Prologue: coefficients + tile 0, one cp.async group.
    {
        if (lane < nf4) {   // c0 is a multiple of 16 floats -> aligned f4 src
            cp16(smem_u32(cc_s) + lane * 16, g_cc + c0 + lane * 4);
            cp16(smem_u32(ia_s) + lane * 16, g_ia + c0 + lane * 4);
            cp16(smem_u32(w_s)  + lane * 16, g_w  + c0 + lane * 4);
        }
        if (lane + 32 < nf4) {
            cp16(smem_u32(cc_s) + (lane + 32) * 16, g_cc + c0 + (lane + 32) * 4);
            cp16(smem_u32(ia_s) + (lane + 32) * 16, g_ia + c0 + (lane + 32) * 4);
            cp16(smem_u32(w_s)  + (lane + 32) * 16, g_w  + c0 + (lane + 32) * 4);
        }
        const float* xb = x + (size_t)(g0 * ROWS) * N + c0;
        #pragma unroll 8
        for (int r = 0; r < ROWS; ++r) {
            uint32_t dst = smem_u32(tile[0] + r * TS);
            cp16(dst + lane * 16, xb + (size_t)r * N + lane * 4);
            if (lane + 32 < nf4)
                cp16(dst + (lane + 32) * 16, xb + (size_t)r * N + (lane + 32) * 4);
        }
        asm volatile("cp.async.commit_group;\n" ::: "memory");
    }

    for (int t = 0; t < RG; ++t) {
        const int buf = t & 1;

        // ---- Prefetch tile t+1 into the other buffer (own cp.async group).
        if (t + 1 < RG) {
            const float* xb = x + (size_t)((g0 + t + 1) * ROWS) * N + c0;
            float* dstbuf = tile[buf ^ 1];
            #pragma unroll 8
            for (int r = 0; r < ROWS; ++r) {
                uint32_t dst = smem_u32(dstbuf + r * TS);
                cp16(dst + lane * 16, xb + (size_t)r * N + lane * 4);
                if (lane + 32 < nf4)
                    cp16(dst + (lane + 32) * 16, xb + (size_t)r * N + (lane + 32) * 4);
            }
            asm volatile("cp.async.commit_group;\n" ::: "memory");
            asm volatile("cp.async.wait_group 1;\n" ::: "memory");  // tile t ready
        } else {
            asm volatile("cp.async.wait_group 0;\n" ::: "memory");
        }
        __syncwarp();

        // ---- Per-thread row solve (thread == row), in place in tile[buf].
        {
            float* tr = tile[buf] + lane * TS;

            // Forward: y[i] = x[i] - y[i-1]*cc[i]; store u = y/a.
            float y = 0.0f;   // exact for c0==0 (cc[0]=0); halo-warmed otherwise
            #pragma unroll 4
            for (int j = 0; j < ncol; j += 4) {
                float4 xv = *(const float4*)(tr + j);
                float4 cv = *(const float4*)(cc_s + j);
                float4 iv = *(const float4*)(ia_s + j);
                float4 u;
                y = fmaf(-y, cv.x, xv.x); u.x = y * iv.x;
                y = fmaf(-y, cv.y, xv.y); u.y = y * iv.y;
                y = fmaf(-y, cv.z, xv.z); u.z = y * iv.z;
                y = fmaf(-y, cv.w, xv.w); u.w = y * iv.w;
                *(float4*)(tr + j) = u;
            }

            // Backward: z[i] = u[i] - w[i]*z[i+1].
            float zv = 0.0f;  // exact for c1==N (w[N-1]=0); halo-warmed otherwise
            #pragma unroll 4
            for (int j = ncol - 4; j >= jlo; j -= 4) {
                float4 uv = *(const float4*)(tr + j);
                float4 wv = *(const float4*)(w_s + j);
                float4 zo;
                zv = fmaf(-zv, wv.w, uv.w); zo.w = zv;
                zv = fmaf(-zv, wv.z, uv.z); zo.z = zv;
                zv = fmaf(-zv, wv.y, uv.y); zo.y = zv;
                zv = fmaf(-zv, wv.x, uv.x); zo.x = zv;
                *(float4*)(tr + j) = zo;
            }
        }
        __syncwarp();

        // ---- Store interior [jlo, jlo+128): lane == f4 column, one row/iter.
        // LDS.128 consecutive within a row (conflict-free), STG.128 512B/warp.
        {
            float* zb = z + (size_t)((g0 + t) * ROWS) * N + s;
            const float* tb = tile[buf] + jlo;
            #pragma unroll 8
            for (int r = 0; r < ROWS; ++r) {
                float4 v = *(const float4*)(tb + r * TS + lane * 4);
                *(float4*)(zb + (size_t)r * N + lane * 4) = v;
            }
        }
        // Reads of tile[buf] complete before the STGs issue, so the next
        // iteration's cp.async into this buffer (issued later in program
        // order) cannot overwrite data still being read.
    }
}

extern "C" void kernel_launch(void* const* d_in, const int* in_sizes, int n_in,
                              void* d_out, int out_size) {
    const float* x = (const float*)d_in[0];
    const float* a = (const float*)d_in[1];
    const float* b = (const float*)d_in[2];
    const float* c = (const float*)d_in[3];
    float* z = (float*)d_out;

    const int N = in_sizes[1];          // 8192
    const int B = in_sizes[0] / N;      // 4096

    setup_coeffs<<<(N + 255) / 256, 256>>>(a, b, c, N);

    dim3 grid(N / L_CHUNK, B / (ROWS * RG));   // 64 x 32 = 2048 blocks
    solve_kernel<<<grid, ROWS>>>(x, z, N);
}

// round 12
// speedup vs baseline: 1.0711x; 1.0711x over previous
#include <cuda_runtime.h>
#include <cstdint>

// Tridiagonal Thomas solve as a register-resident affine warp-scan.
//
// y_i = x_i - cc_i*y_{i-1} and z_i = u_i - w_i*z_{i+1} are affine scans.
// All rows share the same coefficients, so every scan A-multiplier is
// input-independent: precomputed once per block into registers. Per row:
// coalesced LDG -> local FMA pass -> 5-step Kogge-Stone shuffle scan
// (1 shfl + 1 FMA per step) -> fixup -> mirrored backward scan -> coalesced
// STG. No shared memory, no syncthreads, no STS/LDS at all.
//
// Chunking: 128-col interior + 16-col halo each side (decay |c|,|w|<=1/3
// => 0.268^16 ~ 7e-10 warmup error). Columns per warp: segment A = 4/lane
// (cols 4l..4l+3 of the 160), segment B = 1/lane (cols 128+l).
// Coefficient arrays padded +-16 with identity (cc=0, ia=1, w=0) so edge
// chunks need no special cases: cc[0]=0 and w[N-1]=0 give exact boundaries.

#define L_CHUNK 128
#define HALO    16
#define OFF     16
#define MAXN    8192
#define WARPS   4      // warps per block
#define RW      8      // rows per warp

__device__ float g_cc[MAXN + 32];  // padded: idx = col + 16
__device__ float g_ia[MAXN + 32];
__device__ float g_w [MAXN + 32];

__global__ void setup_coeffs(const float* __restrict__ a,
                             const float* __restrict__ b,
                             const float* __restrict__ c, int N) {
    int i = blockIdx.x * blockDim.x + threadIdx.x;   // padded index
    if (i < N + 32) {
        int col = i - OFF;
        if (col >= 0 && col < N) {
            g_cc[i] = (col == 0) ? 0.0f : c[col - 1];
            float ia = 1.0f / a[col];
            g_ia[i] = ia;
            g_w[i]  = (col < N - 1) ? b[col] * ia : 0.0f;
        } else {                     // identity pads
            g_cc[i] = 0.0f; g_ia[i] = 1.0f; g_w[i] = 0.0f;
        }
    }
}

__global__ void __launch_bounds__(WARPS * 32)
solve_kernel(const float* __restrict__ x, float* __restrict__ z, int N) {
    const unsigned FULL = 0xffffffffu;
    const int lane = threadIdx.x & 31;
    const int warp = threadIdx.x >> 5;
    const int s    = blockIdx.x * L_CHUNK;      // interior [s, s+128)
    // padded coefficient index for tile position t is s + t (t in [0,160)).

    // ---- Per-block constant registers -------------------------------------
    const float4 ccA = *(const float4*)(g_cc + s + 4 * lane);
    const float4 iaA = *(const float4*)(g_ia + s + 4 * lane);
    const float4 wA  = *(const float4*)(g_w  + s + 4 * lane);
    const float  ccB = g_cc[s + 128 + lane];
    const float  iaB = g_ia[s + 128 + lane];
    const float  wB  = g_w [s + 128 + lane];

    // Forward in-lane prefix products pa_k = prod_{m<=k}(-cc_{4l+m})
    const float pa0 = -ccA.x;
    const float pa1 = -ccA.y * pa0;
    const float pa2 = -ccA.z * pa1;
    const float pa3 = -ccA.w * pa2;
    // Backward in-lane suffix products qa_k = prod_{m=k..3}(-w_{4l+m})
    const float qa3 = -wA.w;
    const float qa2 = -wA.z * qa3;
    const float qa1 = -wA.y * qa2;
    const float qa0 = -wA.x * qa1;

    // Kogge-Stone A-multiplier snapshots (data-independent, computed once).
    float AfA0,AfA1,AfA2,AfA3,AfA4;          // fwd segA (shfl_up)
    {
        float A = pa3, As;
        AfA0=A; As=__shfl_up_sync(FULL,A,1);  if(lane>=1)  A*=As;
        AfA1=A; As=__shfl_up_sync(FULL,A,2);  if(lane>=2)  A*=As;
        AfA2=A; As=__shfl_up_sync(FULL,A,4);  if(lane>=4)  A*=As;
        AfA3=A; As=__shfl_up_sync(FULL,A,8);  if(lane>=8)  A*=As;
        AfA4=A; As=__shfl_up_sync(FULL,A,16); if(lane>=16) A*=As;
    }
    float AfB0,AfB1,AfB2,AfB3,AfB4, cumAfB;  // fwd segB (shfl_up)
    {
        float A = -ccB, As;
        AfB0=A; As=__shfl_up_sync(FULL,A,1);  if(lane>=1)  A*=As;
        AfB1=A; As=__shfl_up_sync(FULL,A,2);  if(lane>=2)  A*=As;
        AfB2=A; As=__shfl_up_sync(FULL,A,4);  if(lane>=4)  A*=As;
        AfB3=A; As=__shfl_up_sync(FULL,A,8);  if(lane>=8)  A*=As;
        AfB4=A; As=__shfl_up_sync(FULL,A,16); if(lane>=16) A*=As;
        cumAfB = A;                           // prod_{m=0..l}(-ccB_m)
    }
    float AbB0,AbB1,AbB2,AbB3,AbB4;          // bwd segB (shfl_down)
    {
        float A = -wB, As;
        AbB0=A; As=__shfl_down_sync(FULL,A,1);  if(lane+1 <32) A*=As;
        AbB1=A; As=__shfl_down_sync(FULL,A,2);  if(lane+2 <32) A*=As;
        AbB2=A; As=__shfl_down_sync(FULL,A,4);  if(lane+4 <32) A*=As;
        AbB3=A; As=__shfl_down_sync(FULL,A,8);  if(lane+8 <32) A*=As;
        AbB4=A; As=__shfl_down_sync(FULL,A,16); if(lane+16<32) A*=As;
    }
    float AbA0,AbA1,AbA2,AbA3,AbA4, cumAbA;  // bwd segA (shfl_down)
    {
        float A = qa0, As;
        AbA0=A; As=__shfl_down_sync(FULL,A,1);  if(lane+1 <32) A*=As;
        AbA1=A; As=__shfl_down_sync(FULL,A,2);  if(lane+2 <32) A*=As;
        AbA2=A; As=__shfl_down_sync(FULL,A,4);  if(lane+4 <32) A*=As;
        AbA3=A; As=__shfl_down_sync(FULL,A,8);  if(lane+8 <32) A*=As;
        AbA4=A; As=__shfl_down_sync(FULL,A,16); if(lane+16<32) A*=As;
        cumAbA = A;                           // prod_{m=4l..127}(-w_m)
    }

    const bool loadA_ok = (s > 0) || (lane >= 4);     // col = s-16+4l >= 0
    const bool loadB_ok = (s + 112 + lane) < N;       // col = s+112+l < N

    const int rowBase = (blockIdx.y * WARPS + warp) * RW;

    #pragma unroll
    for (int i = 0; i < RW; i += 2) {
        // ---- Load two rows (coalesced LDG.128 + LDG.32) -------------------
        float4 xva[2]; float xBb[2];
        #pragma unroll
        for (int p = 0; p < 2; ++p) {
            const float* xr = x + (size_t)(rowBase + i + p) * N + (s - HALO);
            xva[p] = loadA_ok ? *(const float4*)(xr + 4 * lane)
                              : make_float4(0.f, 0.f, 0.f, 0.f);
            xBb[p] = loadB_ok ? xr[128 + lane] : 0.0f;
        }

        float y0[2], y1[2], y2[2], y3[2], B[2];
        // Forward segA: local pass (carry-in 0 within lane).
        #pragma unroll
        for (int p = 0; p < 2; ++p) {
            y0[p] = xva[p].x;
            y1[p] = fmaf(-ccA.y, y0[p], xva[p].y);
            y2[p] = fmaf(-ccA.z, y1[p], xva[p].z);
            y3[p] = fmaf(-ccA.w, y2[p], xva[p].w);
            B[p]  = y3[p];
        }
        // KS scan, rows interleaved to overlap shfl latency.
        #pragma unroll
        for (int p = 0; p < 2; ++p) { float t=__shfl_up_sync(FULL,B[p],1);  if(lane>=1)  B[p]=fmaf(AfA0,t,B[p]); }
        #pragma unroll
        for (int p = 0; p < 2; ++p) { float t=__shfl_up_sync(FULL,B[p],2);  if(lane>=2)  B[p]=fmaf(AfA1,t,B[p]); }
        #pragma unroll
        for (int p = 0; p < 2; ++p) { float t=__shfl_up_sync(FULL,B[p],4);  if(lane>=4)  B[p]=fmaf(AfA2,t,B[p]); }
        #pragma unroll
        for (int p = 0; p < 2; ++p) { float t=__shfl_up_sync(FULL,B[p],8);  if(lane>=8)  B[p]=fmaf(AfA3,t,B[p]); }
        #pragma unroll
        for (int p = 0; p < 2; ++p) { float t=__shfl_up_sync(FULL,B[p],16); if(lane>=16) B[p]=fmaf(AfA4,t,B[p]); }

        float u0[2],u1[2],u2[2],u3[2], cA[2], BB[2];
        #pragma unroll
        for (int p = 0; p < 2; ++p) {
            float carry = __shfl_up_sync(FULL, B[p], 1);
            if (lane == 0) carry = 0.0f;
            y0[p] = fmaf(pa0, carry, y0[p]);
            y1[p] = fmaf(pa1, carry, y1[p]);
            y2[p] = fmaf(pa2, carry, y2[p]);
            y3[p] = fmaf(pa3, carry, y3[p]);
            u0[p] = y0[p]*iaA.x; u1[p] = y1[p]*iaA.y;
            u2[p] = y2[p]*iaA.z; u3[p] = y3[p]*iaA.w;
            cA[p] = __shfl_sync(FULL, B[p], 31);      // y at t=127
            BB[p] = xBb[p];                            // fwd segB local
        }
        // Forward segB scan.
        #pragma unroll
        for (int p = 0; p < 2; ++p) { float t=__shfl_up_sync(FULL,BB[p],1);  if(lane>=1)  BB[p]=fmaf(AfB0,t,BB[p]); }
        #pragma unroll
        for (int p = 0; p < 2; ++p) { float t=__shfl_up_sync(FULL,BB[p],2);  if(lane>=2)  BB[p]=fmaf(AfB1,t,BB[p]); }
        #pragma unroll
        for (int p = 0; p < 2; ++p) { float t=__shfl_up_sync(FULL,BB[p],4);  if(lane>=4)  BB[p]=fmaf(AfB2,t,BB[p]); }
        #pragma unroll
        for (int p = 0; p < 2; ++p) { float t=__shfl_up_sync(FULL,BB[p],8);  if(lane>=8)  BB[p]=fmaf(AfB3,t,BB[p]); }
        #pragma unroll
        for (int p = 0; p < 2; ++p) { float t=__shfl_up_sync(FULL,BB[p],16); if(lane>=16) BB[p]=fmaf(AfB4,t,BB[p]); }

        float ZB[2];
        #pragma unroll
        for (int p = 0; p < 2; ++p) {
            float yB = fmaf(cumAfB, cA[p], BB[p]);    // + cumA * y_127
            ZB[p] = yB * iaB;                         // u for segB; bwd local
        }
        // Backward segB scan (carry 0 at t=160: right halo truncation).
        #pragma unroll
        for (int p = 0; p < 2; ++p) { float t=__shfl_down_sync(FULL,ZB[p],1);  if(lane+1 <32) ZB[p]=fmaf(AbB0,t,ZB[p]); }
        #pragma unroll
        for (int p = 0; p < 2; ++p) { float t=__shfl_down_sync(FULL,ZB[p],2);  if(lane+2 <32) ZB[p]=fmaf(AbB1,t,ZB[p]); }
        #pragma unroll
        for (int p = 0; p < 2; ++p) { float t=__shfl_down_sync(FULL,ZB[p],4);  if(lane+4 <32) ZB[p]=fmaf(AbB2,t,ZB[p]); }
        #pragma unroll
        for (int p = 0; p < 2; ++p) { float t=__shfl_down_sync(FULL,ZB[p],8);  if(lane+8 <32) ZB[p]=fmaf(AbB3,t,ZB[p]); }
        #pragma unroll
        for (int p = 0; p < 2; ++p) { float t=__shfl_down_sync(FULL,ZB[p],16); if(lane+16<32) ZB[p]=fmaf(AbB4,t,ZB[p]); }

        float z0[2],z1[2],z2[2],z3[2], cB[2], Bz[2];
        #pragma unroll
        for (int p = 0; p < 2; ++p) {
            cB[p] = __shfl_sync(FULL, ZB[p], 0);      // z at t=128
            z3[p] = u3[p];                            // bwd segA local (carry 0)
            z2[p] = fmaf(-wA.z, z3[p], u2[p]);
            z1[p] = fmaf(-wA.y, z2[p], u1[p]);
            z0[p] = fmaf(-wA.x, z1[p], u0[p]);
            Bz[p] = z0[p];
        }
        // Backward segA scan.
        #pragma unroll
        for (int p = 0; p < 2; ++p) { float t=__shfl_down_sync(FULL,Bz[p],1);  if(lane+1 <32) Bz[p]=fmaf(AbA0,t,Bz[p]); }
        #pragma unroll
        for (int p = 0; p < 2; ++p) { float t=__shfl_down_sync(FULL,Bz[p],2);  if(lane+2 <32) Bz[p]=fmaf(AbA1,t,Bz[p]); }
        #pragma unroll
        for (int p = 0; p < 2; ++p) { float t=__shfl_down_sync(FULL,Bz[p],4);  if(lane+4 <32) Bz[p]=fmaf(AbA2,t,Bz[p]); }
        #pragma unroll
        for (int p = 0; p < 2; ++p) { float t=__shfl_down_sync(FULL,Bz[p],8);  if(lane+8 <32) Bz[p]=fmaf(AbA3,t,Bz[p]); }
        #pragma unroll
        for (int p = 0; p < 2; ++p) { float t=__shfl_down_sync(FULL,Bz[p],16); if(lane+16<32) Bz[p]=fmaf(AbA4,t,Bz[p]); }

        // Fixup + store.
        #pragma unroll
        for (int p = 0; p < 2; ++p) {
            float zfull = fmaf(cumAbA, cB[p], Bz[p]); // z at t=4l (final)
            float zc = __shfl_down_sync(FULL, zfull, 1);  // z at t=4(l+1)
            if (lane == 31) zc = cB[p];
            z0[p] = zfull;
            z1[p] = fmaf(qa1, zc, z1[p]);
            z2[p] = fmaf(qa2, zc, z2[p]);
            z3[p] = fmaf(qa3, zc, z3[p]);

            float* zr = z + (size_t)(rowBase + i + p) * N + s;
            if (lane >= 4)           // segA interior: cols s .. s+111
                *(float4*)(zr + 4 * lane - 16) =
                    make_float4(z0[p], z1[p], z2[p], z3[p]);
            if (lane < 16)           // segB interior: cols s+112 .. s+127
                zr[112 + lane] = ZB[p];
        }
    }
}

extern "C" void kernel_launch(void* const* d_in, const int* in_sizes, int n_in,
                              void* d_out, int out_size) {
    const float* x = (const float*)d_in[0];
    const float* a = (const float*)d_in[1];
    const float* b = (const float*)d_in[2];
    const float* c = (const float*)d_in[3];
    float* z = (float*)d_out;

    const int N = in_sizes[1];          // 8192
    const int B = in_sizes[0] / N;      // 4096

    setup_coeffs<<<(N + 32 + 255) / 256, 256>>>(a, b, c, N);

    dim3 grid(N / L_CHUNK, B / (WARPS * RW));   // 64 x 128 = 8192 blocks
    solve_kernel<<<grid, WARPS * 32>>>(x, z, N);
}

// round 13
// speedup vs baseline: 1.0734x; 1.0021x over previous
#include <cuda_runtime.h>
#include <cstdint>

// Tridiagonal Thomas solve as a register-resident affine warp-scan.
// Single kernel: each block derives its own LU-factor window (cc, 1/a, w)
// directly from a,b,c (L2-broadcast), then per row: coalesced LDG ->
// local FMA pass -> 5-step Kogge-Stone shuffle scan (data-independent
// A-multipliers precomputed once per block) -> fixup -> mirrored backward
// scan -> coalesced STG. No shared memory, no syncthreads, no second launch.
//
// Chunking: 128-col interior + 16-col halo each side (decay |c|,|w|<=1/3
// => 0.268^16 ~ 7e-10 warmup error). Segment A = 4 cols/lane (tile cols
// 4l..4l+3), segment B = 1 col/lane (tile col 128+l). Out-of-range columns
// use identity coefficients (cc=0, ia=1, w=0); cc[0]=0 and w[N-1]=0 make
// domain boundaries exact. 4 rows processed per scan pass so the 26-cycle
// SHFL latency is hidden by sibling chains.

#define L_CHUNK 128
#define HALO    16
#define WARPS   4      // warps per block
#define RW      8      // rows per warp
#define P       4      // rows interleaved per scan pass

__global__ void __launch_bounds__(WARPS * 32)
solve_kernel(const float* __restrict__ x, float* __restrict__ z,
             const float* __restrict__ ga, const float* __restrict__ gb,
             const float* __restrict__ gc, int N) {
    const unsigned FULL = 0xffffffffu;
    const int lane = threadIdx.x & 31;
    const int warp = threadIdx.x >> 5;
    const int s    = blockIdx.x * L_CHUNK;      // interior [s, s+128)

    // ---- Per-block coefficients, computed inline (identity padding) -------
    float4 ccA, iaA, wA;
    {
        float cc[4], ia[4], w[4];
        const int colA = s - HALO + 4 * lane;
        #pragma unroll
        for (int k = 0; k < 4; ++k) {
            int col = colA + k;
            bool in = (col >= 0) && (col < N);
            float av = in ? ga[col] : 1.0f;
            cc[k] = (col >= 1 && col < N) ? gc[col - 1] : 0.0f;
            ia[k] = 1.0f / av;
            w[k]  = (col >= 0 && col < N - 1) ? gb[col] * ia[k] : 0.0f;
        }
        ccA = make_float4(cc[0], cc[1], cc[2], cc[3]);
        iaA = make_float4(ia[0], ia[1], ia[2], ia[3]);
        wA  = make_float4(w[0],  w[1],  w[2],  w[3]);
    }
    float ccB, iaB, wB;
    {
        int col = s + 112 + lane;
        bool in = (col >= 0) && (col < N);
        float av = in ? ga[col] : 1.0f;
        ccB = (col >= 1 && col < N) ? gc[col - 1] : 0.0f;
        iaB = 1.0f / av;
        wB  = (col >= 0 && col < N - 1) ? gb[col] * iaB : 0.0f;
    }

    // Forward in-lane prefix products pa_k = prod_{m<=k}(-cc_{4l+m})
    const float pa0 = -ccA.x;
    const float pa1 = -ccA.y * pa0;
    const float pa2 = -ccA.z * pa1;
    const float pa3 = -ccA.w * pa2;
    // Backward in-lane suffix products qa_k = prod_{m=k..3}(-w_{4l+m})
    const float qa3 = -wA.w;
    const float qa2 = -wA.z * qa3;
    const float qa1 = -wA.y * qa2;
    const float qa0 = -wA.x * qa1;

    // Kogge-Stone A-multiplier snapshots (data-independent, once per block).
    float AfA0,AfA1,AfA2,AfA3,AfA4;          // fwd segA (shfl_up)
    {
        float A = pa3, As;
        AfA0=A; As=__shfl_up_sync(FULL,A,1);  if(lane>=1)  A*=As;
        AfA1=A; As=__shfl_up_sync(FULL,A,2);  if(lane>=2)  A*=As;
        AfA2=A; As=__shfl_up_sync(FULL,A,4);  if(lane>=4)  A*=As;
        AfA3=A; As=__shfl_up_sync(FULL,A,8);  if(lane>=8)  A*=As;
        AfA4=A; As=__shfl_up_sync(FULL,A,16); if(lane>=16) A*=As;
    }
    float AfB0,AfB1,AfB2,AfB3,AfB4, cumAfB;  // fwd segB (shfl_up)
    {
        float A = -ccB, As;
        AfB0=A; As=__shfl_up_sync(FULL,A,1);  if(lane>=1)  A*=As;
        AfB1=A; As=__shfl_up_sync(FULL,A,2);  if(lane>=2)  A*=As;
        AfB2=A; As=__shfl_up_sync(FULL,A,4);  if(lane>=4)  A*=As;
        AfB3=A; As=__shfl_up_sync(FULL,A,8);  if(lane>=8)  A*=As;
        AfB4=A; As=__shfl_up_sync(FULL,A,16); if(lane>=16) A*=As;
        cumAfB = A;                           // prod_{m=0..l}(-ccB_m)
    }
    float AbB0,AbB1,AbB2,AbB3,AbB4;          // bwd segB (shfl_down)
    {
        float A = -wB, As;
        AbB0=A; As=__shfl_down_sync(FULL,A,1);  if(lane+1 <32) A*=As;
        AbB1=A; As=__shfl_down_sync(FULL,A,2);  if(lane+2 <32) A*=As;
        AbB2=A; As=__shfl_down_sync(FULL,A,4);  if(lane+4 <32) A*=As;
        AbB3=A; As=__shfl_down_sync(FULL,A,8);  if(lane+8 <32) A*=As;
        AbB4=A; As=__shfl_down_sync(FULL,A,16); if(lane+16<32) A*=As;
    }
    float AbA0,AbA1,AbA2,AbA3,AbA4, cumAbA;  // bwd segA (shfl_down)
    {
        float A = qa0, As;
        AbA0=A; As=__shfl_down_sync(FULL,A,1);  if(lane+1 <32) A*=As;
        AbA1=A; As=__shfl_down_sync(FULL,A,2);  if(lane+2 <32) A*=As;
        AbA2=A; As=__shfl_down_sync(FULL,A,4);  if(lane+4 <32) A*=As;
        AbA3=A; As=__shfl_down_sync(FULL,A,8);  if(lane+8 <32) A*=As;
        AbA4=A; As=__shfl_down_sync(FULL,A,16); if(lane+16<32) A*=As;
        cumAbA = A;                           // prod_{m=4l..127}(-w_m)
    }

    const bool loadA_ok = (s > 0) || (lane >= 4);     // col = s-16+4l >= 0
    const bool loadB_ok = (s + 112 + lane) < N;       // col = s+112+l < N

    const int rowBase = (blockIdx.y * WARPS + warp) * RW;

    #pragma unroll
    for (int i = 0; i < RW; i += P) {
        // ---- Load P rows (coalesced LDG.128 + LDG.32) ---------------------
        float4 xva[P]; float xBb[P];
        #pragma unroll
        for (int p = 0; p < P; ++p) {
            const float* xr = x + (size_t)(rowBase + i + p) * N + (s - HALO);
            xva[p] = loadA_ok ? *(const float4*)(xr + 4 * lane)
                              : make_float4(0.f, 0.f, 0.f, 0.f);
            xBb[p] = loadB_ok ? xr[128 + lane] : 0.0f;
        }

        float y0[P], y1[P], y2[P], y3[P], B[P];
        // Forward segA: local pass (carry-in 0 within lane).
        #pragma unroll
        for (int p = 0; p < P; ++p) {
            y0[p] = xva[p].x;
            y1[p] = fmaf(-ccA.y, y0[p], xva[p].y);
            y2[p] = fmaf(-ccA.z, y1[p], xva[p].z);
            y3[p] = fmaf(-ccA.w, y2[p], xva[p].w);
            B[p]  = y3[p];
        }
        // KS scan, P rows interleaved to overlap shfl latency.
        #pragma unroll
        for (int p = 0; p < P; ++p) { float t=__shfl_up_sync(FULL,B[p],1);  if(lane>=1)  B[p]=fmaf(AfA0,t,B[p]); }
        #pragma unroll
        for (int p = 0; p < P; ++p) { float t=__shfl_up_sync(FULL,B[p],2);  if(lane>=2)  B[p]=fmaf(AfA1,t,B[p]); }
        #pragma unroll
        for (int p = 0; p < P; ++p) { float t=__shfl_up_sync(FULL,B[p],4);  if(lane>=4)  B[p]=fmaf(AfA2,t,B[p]); }
        #pragma unroll
        for (int p = 0; p < P; ++p) { float t=__shfl_up_sync(FULL,B[p],8);  if(lane>=8)  B[p]=fmaf(AfA3,t,B[p]); }
        #pragma unroll
        for (int p = 0; p < P; ++p) { float t=__shfl_up_sync(FULL,B[p],16); if(lane>=16) B[p]=fmaf(AfA4,t,B[p]); }

        float u0[P],u1[P],u2[P],u3[P], cA[P], BB[P];
        #pragma unroll
        for (int p = 0; p < P; ++p) {
            float carry = __shfl_up_sync(FULL, B[p], 1);
            if (lane == 0) carry = 0.0f;
            y0[p] = fmaf(pa0, carry, y0[p]);
            y1[p] = fmaf(pa1, carry, y1[p]);
            y2[p] = fmaf(pa2, carry, y2[p]);
            y3[p] = fmaf(pa3, carry, y3[p]);
            u0[p] = y0[p]*iaA.x; u1[p] = y1[p]*iaA.y;
            u2[p] = y2[p]*iaA.z; u3[p] = y3[p]*iaA.w;
            cA[p] = __shfl_sync(FULL, B[p], 31);      // y at t=127
            BB[p] = xBb[p];                            // fwd segB local
        }
        // Forward segB scan.
        #pragma unroll
        for (int p = 0; p < P; ++p) { float t=__shfl_up_sync(FULL,BB[p],1);  if(lane>=1)  BB[p]=fmaf(AfB0,t,BB[p]); }
        #pragma unroll
        for (int p = 0; p < P; ++p) { float t=__shfl_up_sync(FULL,BB[p],2);  if(lane>=2)  BB[p]=fmaf(AfB1,t,BB[p]); }
        #pragma unroll
        for (int p = 0; p < P; ++p) { float t=__shfl_up_sync(FULL,BB[p],4);  if(lane>=4)  BB[p]=fmaf(AfB2,t,BB[p]); }
        #pragma unroll
        for (int p = 0; p < P; ++p) { float t=__shfl_up_sync(FULL,BB[p],8);  if(lane>=8)  BB[p]=fmaf(AfB3,t,BB[p]); }
        #pragma unroll
        for (int p = 0; p < P; ++p) { float t=__shfl_up_sync(FULL,BB[p],16); if(lane>=16) BB[p]=fmaf(AfB4,t,BB[p]); }

        float ZB[P];
        #pragma unroll
        for (int p = 0; p < P; ++p) {
            float yB = fmaf(cumAfB, cA[p], BB[p]);    // + cumA * y_127
            ZB[p] = yB * iaB;                         // u for segB; bwd local
        }
        // Backward segB scan (carry 0 at t=160: right halo truncation).
        #pragma unroll
        for (int p = 0; p < P; ++p) { float t=__shfl_down_sync(FULL,ZB[p],1);  if(lane+1 <32) ZB[p]=fmaf(AbB0,t,ZB[p]); }
        #pragma unroll
        for (int p = 0; p < P; ++p) { float t=__shfl_down_sync(FULL,ZB[p],2);  if(lane+2 <32) ZB[p]=fmaf(AbB1,t,ZB[p]); }
        #pragma unroll
        for (int p = 0; p < P; ++p) { float t=__shfl_down_sync(FULL,ZB[p],4);  if(lane+4 <32) ZB[p]=fmaf(AbB2,t,ZB[p]); }
        #pragma unroll
        for (int p = 0; p < P; ++p) { float t=__shfl_down_sync(FULL,ZB[p],8);  if(lane+8 <32) ZB[p]=fmaf(AbB3,t,ZB[p]); }
        #pragma unroll
        for (int p = 0; p < P; ++p) { float t=__shfl_down_sync(FULL,ZB[p],16); if(lane+16<32) ZB[p]=fmaf(AbB4,t,ZB[p]); }

        float z0[P],z1[P],z2[P],z3[P], cB[P], Bz[P];
        #pragma unroll
        for (int p = 0; p < P; ++p) {
            cB[p] = __shfl_sync(FULL, ZB[p], 0);      // z at t=128
            z3[p] = u3[p];                            // bwd segA local (carry 0)
            z2[p] = fmaf(-wA.z, z3[p], u2[p]);
            z1[p] = fmaf(-wA.y, z2[p], u1[p]);
            z0[p] = fmaf(-wA.x, z1[p], u0[p]);
            Bz[p] = z0[p];
        }
        // Backward segA scan.
        #pragma unroll
        for (int p = 0; p < P; ++p) { float t=__shfl_down_sync(FULL,Bz[p],1);  if(lane+1 <32) Bz[p]=fmaf(AbA0,t,Bz[p]); }
        #pragma unroll
        for (int p = 0; p < P; ++p) { float t=__shfl_down_sync(FULL,Bz[p],2);  if(lane+2 <32) Bz[p]=fmaf(AbA1,t,Bz[p]); }
        #pragma unroll
        for (int p = 0; p < P; ++p) { float t=__shfl_down_sync(FULL,Bz[p],4);  if(lane+4 <32) Bz[p]=fmaf(AbA2,t,Bz[p]); }
        #pragma unroll
        for (int p = 0; p < P; ++p) { float t=__shfl_down_sync(FULL,Bz[p],8);  if(lane+8 <32) Bz[p]=fmaf(AbA3,t,Bz[p]); }
        #pragma unroll
        for (int p = 0; p < P; ++p) { float t=__shfl_down_sync(FULL,Bz[p],16); if(lane+16<32) Bz[p]=fmaf(AbA4,t,Bz[p]); }

        // Fixup + store.
        #pragma unroll
        for (int p = 0; p < P; ++p) {
            float zfull = fmaf(cumAbA, cB[p], Bz[p]); // z at t=4l (final)
            float zc = __shfl_down_sync(FULL, zfull, 1);  // z at t=4(l+1)
            if (lane == 31) zc = cB[p];
            z0[p] = zfull;
            z1[p] = fmaf(qa1, zc, z1[p]);
            z2[p] = fmaf(qa2, zc, z2[p]);
            z3[p] = fmaf(qa3, zc, z3[p]);

            float* zr = z + (size_t)(rowBase + i + p) * N + s;
            if (lane >= 4)           // segA interior: cols s .. s+111
                *(float4*)(zr + 4 * lane - 16) =
                    make_float4(z0[p], z1[p], z2[p], z3[p]);
            if (lane < 16)           // segB interior: cols s+112 .. s+127
                zr[112 + lane] = ZB[p];
        }
    }
}

extern "C" void kernel_launch(void* const* d_in, const int* in_sizes, int n_in,
                              void* d_out, int out_size) {
    const float* x = (const float*)d_in[0];
    const float* a = (const float*)d_in[1];
    const float* b = (const float*)d_in[2];
    const float* c = (const float*)d_in[3];
    float* z = (float*)d_out;

    const int N = in_sizes[1];          // 8192
    const int B = in_sizes[0] / N;      // 4096

    dim3 grid(N / L_CHUNK, B / (WARPS * RW));   // 64 x 128 = 8192 blocks
    solve_kernel<<<grid, WARPS * 32>>>(x, z, a, b, c, N);
}

// round 14
// speedup vs baseline: 1.1649x; 1.0853x over previous
#include <cuda_runtime.h>
#include <cstdint>

// Tridiagonal Thomas solve with precomputed LU factors, chunked with
// exponential-decay halos (|c|,|w| <= 1/3 => 0.268^16 ~ 7e-10 warmup error).
//
// R14 = R10 (best: warp-autonomous smem pipelines, 16 blocks/SM) + streaming
// stores: z is written with st.global.cs (evict-first) so the 134 MB output
// stream does not thrash the ~L2-resident x (134 MB vs 126 MB L2). Across
// graph replays x then stays hot in L2: DRAM becomes a nearly pure write
// stream and read latency drops to L2 latency.

#define L_CHUNK 64
#define HALO    16
#define CW      (L_CHUNK + 2 * HALO)   // 96 columns max per tile
#define ROWS    32                     // rows per block == threads per block
#define TS      100                    // tile row stride (floats): 25 f4, odd -> conflict-free .128
#define MAXN    8192

__device__ float g_cc[MAXN];   // cc[i] = c[i-1], cc[0] = 0
__device__ float g_ia[MAXN];   // 1 / a[i]
__device__ float g_w [MAXN];   // b[i] / a[i], w[N-1] = 0

__global__ void setup_coeffs(const float* __restrict__ a,
                             const float* __restrict__ b,
                             const float* __restrict__ c, int N) {
    int i = blockIdx.x * blockDim.x + threadIdx.x;
    if (i < N) {
        g_cc[i] = (i == 0) ? 0.0f : c[i - 1];
        float ia = 1.0f / a[i];
        g_ia[i] = ia;
        g_w[i]  = (i < N - 1) ? b[i] * ia : 0.0f;
    }
}

__device__ __forceinline__ uint32_t smem_u32(const void* p) {
    return (uint32_t)__cvta_generic_to_shared(p);
}

__device__ __forceinline__ void cp16(uint32_t dst, const float* src) {
    asm volatile("cp.async.cg.shared.global [%0], [%1], 16;\n"
                 :: "r"(dst), "l"(src));
}

__device__ __forceinline__ void stg128_cs(float* p, float4 v) {
    asm volatile("st.global.cs.v4.f32 [%0], {%1, %2, %3, %4};\n"
                 :: "l"(p), "f"(v.x), "f"(v.y), "f"(v.z), "f"(v.w)
                 : "memory");
}

__global__ void __launch_bounds__(ROWS)
solve_kernel(const float* __restrict__ x, float* __restrict__ z, int N) {
    __shared__ float tile[ROWS * TS];              // 32*100*4 = 12.5 KB
    __shared__ float cc_s[CW], ia_s[CW], w_s[CW];  // 1.15 KB

    const int lane = threadIdx.x;                   // 0..31
    const int s    = blockIdx.x * L_CHUNK;          // chunk start
    const int c0   = max(s - HALO, 0);              // tile col range [c0, c1)
    const int c1   = min(s + L_CHUNK + HALO, N);
    const int ncol = c1 - c0;                       // 80 or 96, multiple of 16
    const int nf4  = ncol >> 2;                     // 20 or 24 float4 per row (<= 32)
    const int jlo  = s - c0;                        // 0 (first chunk) or 16
    const int r0   = blockIdx.y * ROWS;

    // ---- Fire-and-forget async loads: whole tile + coefficients, one group.
    {
        const float* xb = x + (size_t)r0 * N + c0;
        const bool on = lane < nf4;
        #pragma unroll 8
        for (int r = 0; r < ROWS; ++r) {
            if (on)
                cp16(smem_u32(tile + r * TS) + lane * 16,
                     xb + (size_t)r * N + lane * 4);
        }
        if (on) {   // c0 is a multiple of 16 floats -> 16B-aligned sources
            cp16(smem_u32(cc_s) + lane * 16, g_cc + c0 + lane * 4);
            cp16(smem_u32(ia_s) + lane * 16, g_ia + c0 + lane * 4);
            cp16(smem_u32(w_s)  + lane * 16, g_w  + c0 + lane * 4);
        }
        asm volatile("cp.async.commit_group;\n" ::: "memory");
        asm volatile("cp.async.wait_group 0;\n" ::: "memory");
    }
    __syncwarp();

    // ---- Per-thread row solve (thread == row), in place in the tile row.
    {
        float* tr = tile + lane * TS;

        // Forward: y[i] = x[i] - y[i-1]*cc[i]; store u = y/a (off-chain mul).
        float y = 0.0f;   // exact for c0==0 (cc[0]=0); halo-warmed otherwise
        #pragma unroll 4
        for (int j = 0; j < ncol; j += 4) {
            float4 xv = *(const float4*)(tr + j);
            float4 cv = *(const float4*)(cc_s + j);
            float4 iv = *(const float4*)(ia_s + j);
            float4 u;
            y = fmaf(-y, cv.x, xv.x); u.x = y * iv.x;
            y = fmaf(-y, cv.y, xv.y); u.y = y * iv.y;
            y = fmaf(-y, cv.z, xv.z); u.z = y * iv.z;
            y = fmaf(-y, cv.w, xv.w); u.w = y * iv.w;
            *(float4*)(tr + j) = u;
        }

        // Backward: z[i] = u[i] - w[i]*z[i+1]  (single-FMA 4-cycle chain).
        float zv = 0.0f;  // exact for c1==N (w[N-1]=0); halo-warmed otherwise
        #pragma unroll 4
        for (int j = ncol - 4; j >= jlo; j -= 4) {
            float4 uv = *(const float4*)(tr + j);
            float4 wv = *(const float4*)(w_s + j);
            float4 zo;
            zv = fmaf(-zv, wv.w, uv.w); zo.w = zv;
            zv = fmaf(-zv, wv.z, uv.z); zo.z = zv;
            zv = fmaf(-zv, wv.y, uv.y); zo.y = zv;
            zv = fmaf(-zv, wv.x, uv.x); zo.x = zv;
            *(float4*)(tr + j) = zo;
        }
    }
    __syncwarp();

    // ---- Store interior [jlo, jlo+64): 16 f4 per row, 2 rows per warp-iter.
    // LDS.128 conflict-free (row stride 25 f4, odd), STG.128.CS coalesced
    // (evict-first in L2 so the output stream does not evict resident x).
    {
        float* zb = z + (size_t)r0 * N + s;
        const int nout = ROWS * (L_CHUNK / 4);     // 512
        #pragma unroll 16
        for (int i = lane; i < nout; i += 32) {
            int row = i >> 4;
            int c4  = i & 15;
            float4 v = *(const float4*)(tile + row * TS + jlo + c4 * 4);
            stg128_cs(zb + (size_t)row * N + c4 * 4, v);
        }
    }
}

extern "C" void kernel_launch(void* const* d_in, const int* in_sizes, int n_in,
                              void* d_out, int out_size) {
    const float* x = (const float*)d_in[0];
    const float* a = (const float*)d_in[1];
    const float* b = (const float*)d_in[2];
    const float* c = (const float*)d_in[3];
    float* z = (float*)d_out;

    const int N = in_sizes[1];          // 8192
    const int B = in_sizes[0] / N;      // 4096

    setup_coeffs<<<(N + 255) / 256, 256>>>(a, b, c, N);

    dim3 grid(N / L_CHUNK, B / ROWS);   // 128 x 128 = 16384 blocks
    solve_kernel<<<grid, ROWS>>>(x, z, N);
}